// round 1
// baseline (speedup 1.0000x reference)
#include <cuda_runtime.h>

// Problem constants
#define DD 160
#define HH 192
#define WW 160
#define HW (HH * WW)
#define DHW (DD * HH * WW)

// Trilinear sample of a single-channel volume [D,H,W] at normalized coords
// (x,y,z) in [-1,1], align_corners=False, zeros padding.
__device__ __forceinline__ float sample_src(const float* __restrict__ vol,
                                            float x, float y, float z) {
    float ix = ((x + 1.0f) * (float)WW - 1.0f) * 0.5f;
    float iy = ((y + 1.0f) * (float)HH - 1.0f) * 0.5f;
    float iz = ((z + 1.0f) * (float)DD - 1.0f) * 0.5f;
    float fx = floorf(ix), fy = floorf(iy), fz = floorf(iz);
    float wx = ix - fx, wy = iy - fy, wz = iz - fz;
    int x0 = (int)fx, y0 = (int)fy, z0 = (int)fz;

    float acc = 0.0f;
#pragma unroll
    for (int dz = 0; dz < 2; dz++) {
        int zi = z0 + dz;
        if (zi < 0 || zi >= DD) continue;
        float wz_ = dz ? wz : (1.0f - wz);
#pragma unroll
        for (int dy = 0; dy < 2; dy++) {
            int yi = y0 + dy;
            if (yi < 0 || yi >= HH) continue;
            float wy_ = dy ? wy : (1.0f - wy);
            float wzy = wz_ * wy_;
            long base = (long)(zi * HH + yi) * WW;
#pragma unroll
            for (int dx = 0; dx < 2; dx++) {
                int xi = x0 + dx;
                if (xi < 0 || xi >= WW) continue;
                float wx_ = dx ? wx : (1.0f - wx);
                acc += wzy * wx_ * vol[base + xi];
            }
        }
    }
    return acc;
}

// Trilinear sample of a 3-channel volume [3,D,H,W] at normalized coords.
// Returns channels via out pointers. Early-outs if all 8 corners OOB.
__device__ __forceinline__ void sample_flow3(const float* __restrict__ vol,
                                             float x, float y, float z,
                                             float* c0, float* c1, float* c2) {
    *c0 = 0.0f; *c1 = 0.0f; *c2 = 0.0f;
    float ix = ((x + 1.0f) * (float)WW - 1.0f) * 0.5f;
    float iy = ((y + 1.0f) * (float)HH - 1.0f) * 0.5f;
    float iz = ((z + 1.0f) * (float)DD - 1.0f) * 0.5f;
    float fx = floorf(ix), fy = floorf(iy), fz = floorf(iz);
    // Fast reject: any axis fully OOB -> zero contribution
    if (fx < -1.0f || fx > (float)(WW - 1) ||
        fy < -1.0f || fy > (float)(HH - 1) ||
        fz < -1.0f || fz > (float)(DD - 1)) return;
    float wx = ix - fx, wy = iy - fy, wz = iz - fz;
    int x0 = (int)fx, y0 = (int)fy, z0 = (int)fz;

#pragma unroll
    for (int dz = 0; dz < 2; dz++) {
        int zi = z0 + dz;
        if (zi < 0 || zi >= DD) continue;
        float wz_ = dz ? wz : (1.0f - wz);
#pragma unroll
        for (int dy = 0; dy < 2; dy++) {
            int yi = y0 + dy;
            if (yi < 0 || yi >= HH) continue;
            float wy_ = dy ? wy : (1.0f - wy);
            float wzy = wz_ * wy_;
            long base = (long)(zi * HH + yi) * WW;
#pragma unroll
            for (int dx = 0; dx < 2; dx++) {
                int xi = x0 + dx;
                if (xi < 0 || xi >= WW) continue;
                float wcorner = wzy * (dx ? wx : (1.0f - wx));
                long off = base + xi;
                *c0 += wcorner * vol[off];
                *c1 += wcorner * vol[off + DHW];
                *c2 += wcorner * vol[off + 2 * DHW];
            }
        }
    }
}

__global__ void st_fused_kernel(const float* __restrict__ src,
                                const float* __restrict__ flow1,
                                const float* __restrict__ flow2,
                                const float* __restrict__ prf,
                                float* __restrict__ out) {
    int idx = blockIdx.x * blockDim.x + threadIdx.x;
    if (idx >= DHW) return;

    float rf = *prf;

    int w = idx % WW;
    int t = idx / WW;
    int h = t % HH;
    int d = t / HH;

    // flow2 channels (d,h,w)
    float f2d = flow2[idx];
    float f2h = flow2[idx + DHW];
    float f2w = flow2[idx + 2 * DHW];

    // grid2 = to_xyz(grid + flow2*rf)  -> (x,y,z) = (w,h,d) voxel coords (UNNORMALIZED quirk)
    float gx = (float)w + rf * f2w;
    float gy = (float)h + rf * f2h;
    float gz = (float)d + rf * f2d;

    // flow1 warped at grid2 (channels d,h,w). Almost always zero (coords far OOB
    // after the grid_sample unnormalization) — sample_flow3 early-outs.
    float wfd, wfh, wfw;
    sample_flow3(flow1, gx, gy, gz, &wfd, &wfh, &wfw);

    // out_flow = flow1_warped + flow2
    float ofd = wfd + f2d;
    float ofh = wfh + f2h;
    float ofw = wfw + f2w;

    out[DHW + idx]         = ofd;
    out[2 * DHW + idx]     = ofh;
    out[3 * DHW + idx]     = ofw;

    // new_locs_total = 2*((grid + out_flow*rf)/denom - 0.5), denom=(D-1,H-1,W-1)
    float nld = 2.0f * (((float)d + ofd * rf) / (float)(DD - 1) - 0.5f);
    float nlh = 2.0f * (((float)h + ofh * rf) / (float)(HH - 1) - 0.5f);
    float nlw = 2.0f * (((float)w + ofw * rf) / (float)(WW - 1) - 0.5f);

    // to_xyz -> (x,y,z) = (nlw, nlh, nld)
    out[idx] = sample_src(src, nlw, nlh, nld);
}

extern "C" void kernel_launch(void* const* d_in, const int* in_sizes, int n_in,
                              void* d_out, int out_size) {
    const float* src   = (const float*)d_in[0];
    const float* flow1 = (const float*)d_in[1];
    const float* flow2 = (const float*)d_in[2];
    const float* prf   = (const float*)d_in[3];
    float* out = (float*)d_out;

    const int threads = 256;
    const int blocks = (DHW + threads - 1) / threads;
    st_fused_kernel<<<blocks, threads>>>(src, flow1, flow2, prf, out);
}

// round 2
// speedup vs baseline: 1.1023x; 1.1023x over previous
#include <cuda_runtime.h>

// Problem constants
#define DD 160
#define HH 192
#define WW 160
#define HW (HH * WW)
#define DHW (DD * HH * WW)

// Direct-voxel-coord trilinear scale factors (algebraic fold of the
// normalize -> unnormalize round trip, see theory):
//   ix = (w + u) * (W/(W-1)) - 0.5
#define SX (160.0f / 159.0f)
#define SY (192.0f / 191.0f)
#define SZ (160.0f / 159.0f)

// Trilinear sample of single-channel [D,H,W] volume at UNNORMALIZED voxel
// coords (ix,iy,iz), zeros padding. Fast interior path, predicated border path.
__device__ __forceinline__ float sample_src_ix(const float* __restrict__ vol,
                                               float ix, float iy, float iz) {
    float fx = floorf(ix), fy = floorf(iy), fz = floorf(iz);
    float wx = ix - fx, wy = iy - fy, wz = iz - fz;
    int x0 = (int)fx, y0 = (int)fy, z0 = (int)fz;

    if (x0 >= 0 && x0 < WW - 1 && y0 >= 0 && y0 < HH - 1 && z0 >= 0 && z0 < DD - 1) {
        const float* p = vol + ((long)(z0 * HH + y0)) * WW + x0;
        float v000 = p[0],      v001 = p[1];
        float v010 = p[WW],     v011 = p[WW + 1];
        const float* q = p + HW;
        float v100 = q[0],      v101 = q[1];
        float v110 = q[WW],     v111 = q[WW + 1];
        float c00 = fmaf(wx, v001 - v000, v000);
        float c01 = fmaf(wx, v011 - v010, v010);
        float c10 = fmaf(wx, v101 - v100, v100);
        float c11 = fmaf(wx, v111 - v110, v110);
        float c0  = fmaf(wy, c01 - c00, c00);
        float c1  = fmaf(wy, c11 - c10, c10);
        return fmaf(wz, c1 - c0, c0);
    }

    // Border path (zeros padding)
    float acc = 0.0f;
#pragma unroll
    for (int dz = 0; dz < 2; dz++) {
        int zi = z0 + dz;
        if (zi < 0 || zi >= DD) continue;
        float wz_ = dz ? wz : (1.0f - wz);
#pragma unroll
        for (int dy = 0; dy < 2; dy++) {
            int yi = y0 + dy;
            if (yi < 0 || yi >= HH) continue;
            float wy_ = dy ? wy : (1.0f - wy);
            float wzy = wz_ * wy_;
            long base = (long)(zi * HH + yi) * WW;
#pragma unroll
            for (int dx = 0; dx < 2; dx++) {
                int xi = x0 + dx;
                if (xi < 0 || xi >= WW) continue;
                acc += wzy * (dx ? wx : (1.0f - wx)) * vol[base + xi];
            }
        }
    }
    return acc;
}

// Trilinear sample of 3-channel [3,D,H,W] at UNNORMALIZED grid-sample pixel
// coords. Almost always fully OOB here (the reference's un-normalized-grid
// quirk) -> fast reject.
__device__ __forceinline__ void sample_flow3_ix(const float* __restrict__ vol,
                                                float ix, float iy, float iz,
                                                float* c0, float* c1, float* c2) {
    *c0 = 0.0f; *c1 = 0.0f; *c2 = 0.0f;
    if (ix <= -1.0f || ix >= (float)WW ||
        iy <= -1.0f || iy >= (float)HH ||
        iz <= -1.0f || iz >= (float)DD) return;
    float fx = floorf(ix), fy = floorf(iy), fz = floorf(iz);
    float wx = ix - fx, wy = iy - fy, wz = iz - fz;
    int x0 = (int)fx, y0 = (int)fy, z0 = (int)fz;
#pragma unroll
    for (int dz = 0; dz < 2; dz++) {
        int zi = z0 + dz;
        if (zi < 0 || zi >= DD) continue;
        float wz_ = dz ? wz : (1.0f - wz);
#pragma unroll
        for (int dy = 0; dy < 2; dy++) {
            int yi = y0 + dy;
            if (yi < 0 || yi >= HH) continue;
            float wzy = wz_ * (dy ? wy : (1.0f - wy));
#pragma unroll
            for (int dx = 0; dx < 2; dx++) {
                int xi = x0 + dx;
                if (xi < 0 || xi >= WW) continue;
                float wc = wzy * (dx ? wx : (1.0f - wx));
                long off = (long)(zi * HH + yi) * WW + xi;
                *c0 += wc * vol[off];
                *c1 += wc * vol[off + DHW];
                *c2 += wc * vol[off + 2 * DHW];
            }
        }
    }
}

__global__ void __launch_bounds__(256)
st_fused4_kernel(const float* __restrict__ src,
                 const float* __restrict__ flow1,
                 const float* __restrict__ flow2,
                 const float* __restrict__ prf,
                 float* __restrict__ out) {
    int tid = blockIdx.x * blockDim.x + threadIdx.x;
    int idx = tid * 4;
    if (idx >= DHW) return;

    float rf = *prf;

    // 4 consecutive voxels share (d,h); w..w+3 in one row (WW % 4 == 0)
    int w = idx % WW;
    int t = idx / WW;
    int h = t % HH;
    int d = t / HH;

    float4 v_f2d = *(const float4*)(flow2 + idx);
    float4 v_f2h = *(const float4*)(flow2 + idx + DHW);
    float4 v_f2w = *(const float4*)(flow2 + idx + 2 * DHW);

    float f2d[4] = {v_f2d.x, v_f2d.y, v_f2d.z, v_f2d.w};
    float f2h[4] = {v_f2h.x, v_f2h.y, v_f2h.z, v_f2h.w};
    float f2w[4] = {v_f2w.x, v_f2w.y, v_f2w.z, v_f2w.w};

    float ofd[4], ofh[4], ofw[4], res[4];

#pragma unroll
    for (int i = 0; i < 4; i++) {
        float wf = (float)(w + i);
        // grid2 (voxel coords, unnormalized quirk): (x,y,z) = (w,h,d)+rf*flow2_{w,h,d}
        float gx = fmaf(rf, f2w[i], wf);
        float gy = fmaf(rf, f2h[i], (float)h);
        float gz = fmaf(rf, f2d[i], (float)d);
        // grid_sample unnormalization of those (treated as normalized coords)
        float ix1 = fmaf(gx + 1.0f, (float)WW * 0.5f, -0.5f);
        float iy1 = fmaf(gy + 1.0f, (float)HH * 0.5f, -0.5f);
        float iz1 = fmaf(gz + 1.0f, (float)DD * 0.5f, -0.5f);

        float wfd, wfh, wfw;
        sample_flow3_ix(flow1, ix1, iy1, iz1, &wfd, &wfh, &wfw);

        ofd[i] = wfd + f2d[i];
        ofh[i] = wfh + f2h[i];
        ofw[i] = wfw + f2w[i];

        // Direct pixel coords for the src sample (division-free fold)
        float ix = fmaf(fmaf(rf, ofw[i], wf),       SX, -0.5f);
        float iy = fmaf(fmaf(rf, ofh[i], (float)h), SY, -0.5f);
        float iz = fmaf(fmaf(rf, ofd[i], (float)d), SZ, -0.5f);

        res[i] = sample_src_ix(src, ix, iy, iz);
    }

    *(float4*)(out + idx)           = make_float4(res[0], res[1], res[2], res[3]);
    *(float4*)(out + DHW + idx)     = make_float4(ofd[0], ofd[1], ofd[2], ofd[3]);
    *(float4*)(out + 2 * DHW + idx) = make_float4(ofh[0], ofh[1], ofh[2], ofh[3]);
    *(float4*)(out + 3 * DHW + idx) = make_float4(ofw[0], ofw[1], ofw[2], ofw[3]);
}

extern "C" void kernel_launch(void* const* d_in, const int* in_sizes, int n_in,
                              void* d_out, int out_size) {
    const float* src   = (const float*)d_in[0];
    const float* flow1 = (const float*)d_in[1];
    const float* flow2 = (const float*)d_in[2];
    const float* prf   = (const float*)d_in[3];
    float* out = (float*)d_out;

    const int threads = 256;
    const int nthreads_total = DHW / 4;
    const int blocks = (nthreads_total + threads - 1) / threads;
    st_fused4_kernel<<<blocks, threads>>>(src, flow1, flow2, prf, out);
}